// round 1
// baseline (speedup 1.0000x reference)
#include <cuda_runtime.h>
#include <cstdint>

// 2D Haar DWT, one level.
// Input:  x  (16,1,2048,2048) fp32
// Output: [ll | lh | hl | hh], each (16,1,1024,1024) fp32, concatenated.
//
// Thread mapping: thread t handles batch b, output row i, output column pair
// (2*j2, 2*j2+1). It loads float4 from input rows 2i and 2i+1 at column 4*j2,
// giving two 2x2 blocks, and writes one float2 per band.

static __device__ __forceinline__ float safef(float v) {
    // _safe: non-finite -> 0.0f
    return isfinite(v) ? v : 0.0f;
}

__global__ void __launch_bounds__(256) dwt2d_haar_kernel(
    const float* __restrict__ x, float* __restrict__ out)
{
    constexpr int W  = 2048;   // input width
    constexpr int Wo = 1024;   // output width
    constexpr int Ho = 1024;   // output height
    constexpr int JP = Wo / 2; // 512 column-pairs per output row
    const long long NB = 16LL * Ho * Wo; // elements per band

    long long t = (long long)blockIdx.x * blockDim.x + threadIdx.x;
    // t in [0, 16*1024*512)
    int j2 = (int)(t & (JP - 1));        // column-pair index, 0..511
    long long rest = t >> 9;
    int i  = (int)(rest & (Ho - 1));     // output row, 0..1023
    long long b = rest >> 10;            // batch, 0..15

    const float4* row0 = reinterpret_cast<const float4*>(
        x + (b * W + 2LL * i) * W);
    const float4* row1 = reinterpret_cast<const float4*>(
        x + (b * W + 2LL * i + 1) * W);

    float4 r0 = row0[j2];
    float4 r1 = row1[j2];

    float a0 = safef(r0.x), b0 = safef(r0.y);
    float c0 = safef(r1.x), d0 = safef(r1.y);
    float a1 = safef(r0.z), b1 = safef(r0.w);
    float c1 = safef(r1.z), d1 = safef(r1.w);

    const float h = 0.5f;
    float2 ll, lh, hl, hh;
    ll.x = h * ( a0 + b0 + c0 + d0);
    lh.x = h * (-a0 + b0 - c0 + d0);
    hl.x = h * (-a0 - b0 + c0 + d0);
    hh.x = h * ( a0 - b0 - c0 + d0);
    ll.y = h * ( a1 + b1 + c1 + d1);
    lh.y = h * (-a1 + b1 - c1 + d1);
    hl.y = h * (-a1 - b1 + c1 + d1);
    hh.y = h * ( a1 - b1 - c1 + d1);

    // outputs of finite inputs are finite, but mirror reference _safe exactly
    ll.x = safef(ll.x); ll.y = safef(ll.y);
    lh.x = safef(lh.x); lh.y = safef(lh.y);
    hl.x = safef(hl.x); hl.y = safef(hl.y);
    hh.x = safef(hh.x); hh.y = safef(hh.y);

    long long o = (b * Ho + i) * Wo + 2LL * j2; // element offset within a band
    float2* po = reinterpret_cast<float2*>(out);
    long long o2 = o >> 1;           // float2 offset
    long long nb2 = NB >> 1;         // float2 elements per band

    po[o2]           = ll;
    po[o2 + nb2]     = lh;
    po[o2 + 2 * nb2] = hl;
    po[o2 + 3 * nb2] = hh;
}

extern "C" void kernel_launch(void* const* d_in, const int* in_sizes, int n_in,
                              void* d_out, int out_size)
{
    const float* x = (const float*)d_in[0];
    float* out = (float*)d_out;

    const long long total_threads = 16LL * 1024 * 512; // 8,388,608
    const int block = 256;
    const long long grid = total_threads / block;       // 32768

    dwt2d_haar_kernel<<<(unsigned)grid, block>>>(x, out);
}